// round 4
// baseline (speedup 1.0000x reference)
#include <cuda_runtime.h>
#include <cuda_fp16.h>
#include <math.h>

// ----------------------------------------------------------------------------
// TimeSeriesRNN: 2-layer LSTM encoder (T=256) + decoder (T=32) with projection
// B=64, V=64, H=1024. Persistent-kernel, fp16 mma.m16n8k16, fragment-order
// global layouts. R3: 8 warps with K-split x2 + smem reduce; W stays in L1
// (__ldg), activations bypass L1 (__ldcg).
// ----------------------------------------------------------------------------

#define B_    64
#define TIN   256
#define V_    64
#define H_    1024
#define TOUT  32
#define NCTA  128
#define NTHR  256     // 8 warps: w = m-tile(0..3) + 4*khalf(0..1)

// Fragment-order device buffers (all sized in __half elements)
__device__ __align__(16) __half g_W0f[4456448];   // 4096 x 1088
__device__ __align__(16) __half g_W1f[8388608];   // 4096 x 2048
__device__ __align__(16) __half g_Wff[65536];     // 64 x 1024
__device__ __align__(16) __half g_XF [1048576];   // x in A-frag order
__device__ __align__(16) __half g_H0F[131072];    // ping-pong h0
__device__ __align__(16) __half g_H1F[131072];    // ping-pong h1
__device__ __align__(16) __half g_INPF[4096];     // decoder feedback input

__device__ unsigned g_bar_count = 0;
__device__ unsigned g_bar_gen   = 0;

// ----------------------------------------------------------------------------
__device__ __forceinline__ void mma16816(float* d, const uint4& a,
                                         unsigned b0, unsigned b1) {
    asm volatile(
        "mma.sync.aligned.m16n8k16.row.col.f32.f16.f16.f32 "
        "{%0,%1,%2,%3}, {%4,%5,%6,%7}, {%8,%9}, {%0,%1,%2,%3};\n"
        : "+f"(d[0]), "+f"(d[1]), "+f"(d[2]), "+f"(d[3])
        : "r"(a.x), "r"(a.y), "r"(a.z), "r"(a.w), "r"(b0), "r"(b1));
}

__device__ __forceinline__ float sigm(float x) { return 1.0f / (1.0f + __expf(-x)); }

__device__ __forceinline__ void grid_sync() {
    __syncthreads();
    if (threadIdx.x == 0) {
        unsigned gen;
        asm volatile("ld.acquire.gpu.u32 %0, [%1];" : "=r"(gen) : "l"(&g_bar_gen) : "memory");
        __threadfence();
        unsigned t = atomicAdd(&g_bar_count, 1u);
        if (t == gridDim.x - 1) {
            g_bar_count = 0;
            asm volatile("st.release.gpu.u32 [%0], %1;" :: "l"(&g_bar_gen), "r"(gen + 1u) : "memory");
        } else {
            unsigned cur;
            do {
                asm volatile("ld.acquire.gpu.u32 %0, [%1];" : "=r"(cur) : "l"(&g_bar_gen) : "memory");
            } while (cur == gen);
        }
        __threadfence();
    }
    __syncthreads();
}

// ----------------------------------------------------------------------------
// prep kernels (unchanged layouts from R2 — verified correct)
// ----------------------------------------------------------------------------
__global__ void prep_w0_kernel(const float* __restrict__ W) {
    const int total = 4456448, K = 1088, nchunk = 68;
    for (int f = blockIdx.x * blockDim.x + threadIdx.x; f < total; f += gridDim.x * blockDim.x) {
        int e = f & 1, q = (f >> 1) & 3, l = (f >> 3) & 31, ng = (f >> 8) & 1;
        int rest = f >> 9;
        int c = rest % nchunk, ct = rest / nchunk;
        int n = (ng << 4) + ((q >> 1) << 3) + (l >> 2);
        int k = (c << 4) + ((q & 1) << 3) + ((l & 3) << 1) + e;
        int j = (ct << 3) + (n >> 2);
        int gate = n & 3;
        g_W0f[f] = __float2half(W[(size_t)(gate * 1024 + j) * K + k]);
    }
}

__global__ void prep_w1_kernel(const float* __restrict__ W) {
    const int total = 8388608, K = 2048;
    for (int f = blockIdx.x * blockDim.x + threadIdx.x; f < total; f += gridDim.x * blockDim.x) {
        int e = f & 1, q = (f >> 1) & 3, l = (f >> 3) & 31, ng = (f >> 8) & 1;
        int rest = f >> 9;
        int c = rest & 127, ct = rest >> 7;
        int n = (ng << 4) + ((q >> 1) << 3) + (l >> 2);
        int k = (c << 4) + ((q & 1) << 3) + ((l & 3) << 1) + e;
        int j = (ct << 3) + (n >> 2);
        int gate = n & 3;
        g_W1f[f] = __float2half(W[(size_t)(gate * 1024 + j) * K + k]);
    }
}

__global__ void prep_wf_kernel(const float* __restrict__ Wf) {
    const int total = 65536;
    for (int f = blockIdx.x * blockDim.x + threadIdx.x; f < total; f += gridDim.x * blockDim.x) {
        int e = f & 1, q = (f >> 1) & 3, l = (f >> 3) & 31;
        int rest = f >> 8;
        int c = rest & 63, vg = rest >> 6;
        int v = (vg << 4) + ((q >> 1) << 3) + (l >> 2);
        int j = (c << 4) + ((q & 1) << 3) + ((l & 3) << 1) + e;
        g_Wff[f] = __float2half(Wf[(size_t)v * 1024 + j]);
    }
}

__global__ void prep_x_kernel(const float* __restrict__ x) {
    const int total = 1048576;
    for (int f = blockIdx.x * blockDim.x + threadIdx.x; f < total; f += gridDim.x * blockDim.x) {
        int e = f & 1, q = (f >> 1) & 3, l = (f >> 3) & 31;
        int rest = f >> 8;
        int c = rest & 3, m = (rest >> 2) & 3, t = rest >> 4;
        int b = (m << 4) + ((q & 1) << 3) + (l >> 2);
        int v = (c << 4) + ((q >> 1) << 3) + ((l & 3) << 1) + e;
        g_XF[f] = __float2half(x[(size_t)(b * TIN + t) * V_ + v]);
    }
}

// ----------------------------------------------------------------------------
// GEMM over assigned chunk range [start, end) of the concatenated A0|A1 input.
// W via __ldg (L1-resident), A via __ldcg (L2-only).
// ----------------------------------------------------------------------------
__device__ __forceinline__ void gemm_range(
    const __half* __restrict__ Wb,
    const __half* __restrict__ A0, int n0,
    const __half* __restrict__ A1,
    int start, int end, float acc[4][4], int lane)
{
    int e0 = min(end, n0);
    {
        const __half* a  = A0 + (size_t)start * 256 + lane * 8;
        const __half* wl = Wb + (size_t)start * 512 + lane * 8;
#pragma unroll 4
        for (int c = start; c < e0; ++c) {
            uint4 av = __ldcg((const uint4*)a);
            uint4 w0 = __ldg((const uint4*)wl);
            uint4 w1 = __ldg((const uint4*)(wl + 256));
            mma16816(acc[0], av, w0.x, w0.y);
            mma16816(acc[1], av, w0.z, w0.w);
            mma16816(acc[2], av, w1.x, w1.y);
            mma16816(acc[3], av, w1.z, w1.w);
            a += 256; wl += 512;
        }
    }
    int s1 = max(start, n0);
    {
        const __half* a  = A1 + (size_t)(s1 - n0) * 256 + lane * 8;
        const __half* wl = Wb + (size_t)s1 * 512 + lane * 8;
#pragma unroll 4
        for (int c = s1; c < end; ++c) {
            uint4 av = __ldcg((const uint4*)a);
            uint4 w0 = __ldg((const uint4*)wl);
            uint4 w1 = __ldg((const uint4*)(wl + 256));
            mma16816(acc[0], av, w0.x, w0.y);
            mma16816(acc[1], av, w0.z, w0.w);
            mma16816(acc[2], av, w1.x, w1.y);
            mma16816(acc[3], av, w1.z, w1.w);
            a += 256; wl += 512;
        }
    }
}

// ----------------------------------------------------------------------------
// one LSTM cell phase: K split across warp pairs (w, w+4); kh=1 writes partials
// to smem, kh=0 reduces + runs the cell nonlinearity + writes h (frag order).
// ----------------------------------------------------------------------------
__device__ __forceinline__ void cell_phase(
    const __half* __restrict__ Wb,
    const __half* __restrict__ A0, int n0,
    const __half* __restrict__ A1, int n1,
    const float*  __restrict__ bias,
    float* cr, __half* __restrict__ hout,
    float* __restrict__ red,
    int ct, int w, int kh, int m, int lane)
{
    float acc[4][4];
#pragma unroll
    for (int i = 0; i < 4; ++i)
#pragma unroll
        for (int k = 0; k < 4; ++k) acc[i][k] = 0.0f;

    const int total = n0 + n1;
    const int h = (total + 1) >> 1;
    gemm_range(Wb, A0, n0, A1, kh ? h : 0, kh ? total : h, acc, lane);

    if (kh) {
        float* dst = red + (size_t)m * 512 + lane * 16;
#pragma unroll
        for (int i = 0; i < 4; ++i)
#pragma unroll
            for (int k = 0; k < 4; ++k) dst[i * 4 + k] = acc[i][k];
    }
    __syncthreads();
    if (kh) return;

    const float* src = red + (size_t)m * 512 + lane * 16;
#pragma unroll
    for (int i = 0; i < 4; ++i)
#pragma unroll
        for (int k = 0; k < 4; ++k) acc[i][k] += src[i * 4 + k];

    const bool hi = (lane & 1);
#pragma unroll
    for (int nt = 0; nt < 4; ++nt) {
        float d0 = acc[nt][0], d1 = acc[nt][1], d2 = acc[nt][2], d3 = acc[nt][3];
        int jl = 2 * nt + ((lane & 3) >> 1);
        int j  = ct * 8 + jl;
        int g0 = (lane & 1) * 2;
        float bv0 = __ldg(bias + g0 * 1024 + j);
        float bv1 = __ldg(bias + (g0 + 1) * 1024 + j);
        d0 += bv0; d1 += bv1; d2 += bv0; d3 += bv1;

        float sA = hi ? d0 : d2;
        float sB = hi ? d1 : d3;
        float rA = __shfl_xor_sync(0xffffffffu, sA, 1);
        float rB = __shfl_xor_sync(0xffffffffu, sB, 1);
        float gi = hi ? rA : d0;
        float gf = hi ? rB : d1;
        float gc = hi ? d2 : rA;
        float go = hi ? d3 : rB;

        float cn = sigm(gf) * cr[nt] + sigm(gi) * tanhf(gc);
        cr[nt] = cn;
        float hv = sigm(go) * tanhf(cn);

        int b = m * 16 + (lane >> 2) + (hi ? 8 : 0);
        int ldst = ((b & 7) << 2) + ((j & 7) >> 1);
        int qq = (hi ? 1 : 0) + ((j & 8) ? 2 : 0);
        hout[(size_t)((b >> 4) * 64 + (j >> 4)) * 256 + ldst * 8 + qq * 2 + (j & 1)] =
            __float2half(hv);
    }
}

// ----------------------------------------------------------------------------
// main persistent kernel
// ----------------------------------------------------------------------------
__global__ void __launch_bounds__(NTHR, 1)
rnn_main_kernel(const float* __restrict__ b0, const float* __restrict__ b1,
                const float* __restrict__ bf, float* __restrict__ out)
{
    const int ct   = blockIdx.x;
    const int tid  = threadIdx.x;
    const int w    = tid >> 5;
    const int lane = tid & 31;
    const int m    = w & 3;
    const int kh   = w >> 2;

    float c0r[4] = {0.f, 0.f, 0.f, 0.f};
    float c1r[4] = {0.f, 0.f, 0.f, 0.f};

    const __half* Wb0 = g_W0f + (size_t)ct * 68 * 512;
    const __half* Wb1 = g_W1f + (size_t)ct * 128 * 512;

    __shared__ float red[2048];   // 8 KB: cell k-reduce (4x512) / projection (7x256)

    for (int s = 0; s < TIN + TOUT; ++s) {
        const int p   = s & 1;
        const bool dec = (s >= TIN);

        // ---- layer 0: input = [x_t | h0_old] ----
        const __half* a0base;
        if (!dec)            a0base = g_XF + (size_t)(s * 4 + m) * 4 * 256;
        else if (s == TIN)   a0base = g_XF + (size_t)(255 * 4 + m) * 4 * 256;
        else                 a0base = g_INPF + (size_t)m * 4 * 256;
        const __half* h0old = g_H0F + (size_t)(p * 4 + m) * 16384;
        __half* h0out = g_H0F + (size_t)(1 - p) * 65536;
        cell_phase(Wb0, a0base, 4, h0old, (s > 0) ? 64 : 0, b0, c0r, h0out,
                   red, ct, w, kh, m, lane);
        grid_sync();

        // ---- layer 1: input = [h0_new | h1_old] ----
        const __half* h0new = g_H0F + (size_t)((1 - p) * 4 + m) * 16384;
        const __half* h1old = g_H1F + (size_t)(p * 4 + m) * 16384;
        __half* h1out = g_H1F + (size_t)(1 - p) * 65536;
        cell_phase(Wb1, h0new, 64, h1old, (s > 0) ? 64 : 0, b1, c1r, h1out,
                   red, ct, w, kh, m, lane);
        grid_sync();

        // ---- decoder projection: out = h1 @ Wf^T + bf ----
        if (dec) {
            if (ct < 16) {
                const int mm = ct & 3, vg = ct >> 2;
                // warp w handles K-chunks [w*8, w*8+8) of 64
                const __half* A  = g_H1F + (size_t)((1 - p) * 4 + mm) * 16384
                                   + (size_t)(w * 8) * 256 + lane * 8;
                const __half* Wp = g_Wff + (size_t)(vg * 64 + w * 8) * 256 + lane * 8;
                float pacc[8];
#pragma unroll
                for (int k = 0; k < 8; ++k) pacc[k] = 0.0f;
#pragma unroll
                for (int cc = 0; cc < 8; ++cc) {
                    uint4 av = __ldcg((const uint4*)(A  + (size_t)cc * 256));
                    uint4 wv = __ldg ((const uint4*)(Wp + (size_t)cc * 256));
                    mma16816(pacc + 0, av, wv.x, wv.y);
                    mma16816(pacc + 4, av, wv.z, wv.w);
                }
                if (w > 0) {
                    float* dst = red + (size_t)(w - 1) * 256 + lane * 8;
#pragma unroll
                    for (int k = 0; k < 8; ++k) dst[k] = pacc[k];
                }
                __syncthreads();
                if (w == 0) {
                    float fsum[8];
#pragma unroll
                    for (int k = 0; k < 8; ++k) fsum[k] = pacc[k];
#pragma unroll
                    for (int ww = 1; ww < 8; ++ww) {
                        const float* src = red + (size_t)(ww - 1) * 256 + lane * 8;
#pragma unroll
                        for (int k = 0; k < 8; ++k) fsum[k] += src[k];
                    }
                    const int tdec = s - TIN;
#pragma unroll
                    for (int nt = 0; nt < 2; ++nt)
#pragma unroll
                        for (int rr = 0; rr < 2; ++rr)
#pragma unroll
                            for (int e2 = 0; e2 < 2; ++e2) {
                                int b = mm * 16 + (lane >> 2) + rr * 8;
                                int v = vg * 16 + nt * 8 + ((lane & 3) << 1) + e2;
                                float val = fsum[nt * 4 + rr * 2 + e2] + __ldg(bf + v);
                                out[(size_t)(b * TOUT + tdec) * V_ + v] = val;
                                g_INPF[(size_t)((b >> 4) * 4 + (v >> 4)) * 256
                                       + (((b & 7) << 2) + ((v & 7) >> 1)) * 8
                                       + (rr + ((v & 8) ? 2 : 0)) * 2 + (v & 1)] =
                                    __float2half(val);
                            }
                }
            }
            grid_sync();
        }
    }
}

// ----------------------------------------------------------------------------
extern "C" void kernel_launch(void* const* d_in, const int* in_sizes, int n_in,
                              void* d_out, int out_size) {
    const float* x  = (const float*)d_in[0];
    const float* W0 = (const float*)d_in[1];
    const float* b0 = (const float*)d_in[2];
    const float* W1 = (const float*)d_in[3];
    const float* b1 = (const float*)d_in[4];
    const float* Wf = (const float*)d_in[5];
    const float* bf = (const float*)d_in[6];
    float* out = (float*)d_out;

    prep_w0_kernel<<<2048, 256>>>(W0);
    prep_w1_kernel<<<4096, 256>>>(W1);
    prep_wf_kernel<<<64, 256>>>(Wf);
    prep_x_kernel<<<1024, 256>>>(x);
    rnn_main_kernel<<<NCTA, NTHR>>>(b0, b1, bf, out);
}

// round 5
// speedup vs baseline: 1.4120x; 1.4120x over previous
#include <cuda_runtime.h>
#include <cuda_fp16.h>
#include <math.h>

// ----------------------------------------------------------------------------
// TimeSeriesRNN: 2-layer LSTM encoder (T=256) + decoder (T=32) with projection
// B=64, V=64, H=1024. Persistent-kernel, fp16 mma.m16n8k16, fragment-order
// global layouts. R3: 8 warps with K-split x2 + smem reduce; W stays in L1
// (__ldg), activations bypass L1 (__ldcg).
// ----------------------------------------------------------------------------

#define B_    64
#define TIN   256
#define V_    64
#define H_    1024
#define TOUT  32
#define NCTA  128
#define NTHR  256     // 8 warps: w = m-tile(0..3) + 4*khalf(0..1)

// Fragment-order device buffers (all sized in __half elements)
__device__ __align__(16) __half g_W0f[4456448];   // 4096 x 1088
__device__ __align__(16) __half g_W1f[8388608];   // 4096 x 2048
__device__ __align__(16) __half g_Wff[65536];     // 64 x 1024
__device__ __align__(16) __half g_XF [1048576];   // x in A-frag order
__device__ __align__(16) __half g_H0F[131072];    // ping-pong h0
__device__ __align__(16) __half g_H1F[131072];    // ping-pong h1
__device__ __align__(16) __half g_INPF[4096];     // decoder feedback input

__device__ unsigned g_bar_count = 0;
__device__ unsigned g_bar_gen   = 0;

// ----------------------------------------------------------------------------
__device__ __forceinline__ void mma16816(float* d, const uint4& a,
                                         unsigned b0, unsigned b1) {
    asm volatile(
        "mma.sync.aligned.m16n8k16.row.col.f32.f16.f16.f32 "
        "{%0,%1,%2,%3}, {%4,%5,%6,%7}, {%8,%9}, {%0,%1,%2,%3};\n"
        : "+f"(d[0]), "+f"(d[1]), "+f"(d[2]), "+f"(d[3])
        : "r"(a.x), "r"(a.y), "r"(a.z), "r"(a.w), "r"(b0), "r"(b1));
}

__device__ __forceinline__ float sigm(float x) { return 1.0f / (1.0f + __expf(-x)); }

__device__ __forceinline__ void grid_sync() {
    __syncthreads();
    if (threadIdx.x == 0) {
        unsigned gen;
        asm volatile("ld.acquire.gpu.u32 %0, [%1];" : "=r"(gen) : "l"(&g_bar_gen) : "memory");
        __threadfence();
        unsigned t = atomicAdd(&g_bar_count, 1u);
        if (t == gridDim.x - 1) {
            g_bar_count = 0;
            asm volatile("st.release.gpu.u32 [%0], %1;" :: "l"(&g_bar_gen), "r"(gen + 1u) : "memory");
        } else {
            unsigned cur;
            do {
                asm volatile("ld.acquire.gpu.u32 %0, [%1];" : "=r"(cur) : "l"(&g_bar_gen) : "memory");
            } while (cur == gen);
        }
        __threadfence();
    }
    __syncthreads();
}

// ----------------------------------------------------------------------------
// prep kernels (unchanged layouts from R2 — verified correct)
// ----------------------------------------------------------------------------
__global__ void prep_w0_kernel(const float* __restrict__ W) {
    const int total = 4456448, K = 1088, nchunk = 68;
    for (int f = blockIdx.x * blockDim.x + threadIdx.x; f < total; f += gridDim.x * blockDim.x) {
        int e = f & 1, q = (f >> 1) & 3, l = (f >> 3) & 31, ng = (f >> 8) & 1;
        int rest = f >> 9;
        int c = rest % nchunk, ct = rest / nchunk;
        int n = (ng << 4) + ((q >> 1) << 3) + (l >> 2);
        int k = (c << 4) + ((q & 1) << 3) + ((l & 3) << 1) + e;
        int j = (ct << 3) + (n >> 2);
        int gate = n & 3;
        g_W0f[f] = __float2half(W[(size_t)(gate * 1024 + j) * K + k]);
    }
}

__global__ void prep_w1_kernel(const float* __restrict__ W) {
    const int total = 8388608, K = 2048;
    for (int f = blockIdx.x * blockDim.x + threadIdx.x; f < total; f += gridDim.x * blockDim.x) {
        int e = f & 1, q = (f >> 1) & 3, l = (f >> 3) & 31, ng = (f >> 8) & 1;
        int rest = f >> 9;
        int c = rest & 127, ct = rest >> 7;
        int n = (ng << 4) + ((q >> 1) << 3) + (l >> 2);
        int k = (c << 4) + ((q & 1) << 3) + ((l & 3) << 1) + e;
        int j = (ct << 3) + (n >> 2);
        int gate = n & 3;
        g_W1f[f] = __float2half(W[(size_t)(gate * 1024 + j) * K + k]);
    }
}

__global__ void prep_wf_kernel(const float* __restrict__ Wf) {
    const int total = 65536;
    for (int f = blockIdx.x * blockDim.x + threadIdx.x; f < total; f += gridDim.x * blockDim.x) {
        int e = f & 1, q = (f >> 1) & 3, l = (f >> 3) & 31;
        int rest = f >> 8;
        int c = rest & 63, vg = rest >> 6;
        int v = (vg << 4) + ((q >> 1) << 3) + (l >> 2);
        int j = (c << 4) + ((q & 1) << 3) + ((l & 3) << 1) + e;
        g_Wff[f] = __float2half(Wf[(size_t)v * 1024 + j]);
    }
}

__global__ void prep_x_kernel(const float* __restrict__ x) {
    const int total = 1048576;
    for (int f = blockIdx.x * blockDim.x + threadIdx.x; f < total; f += gridDim.x * blockDim.x) {
        int e = f & 1, q = (f >> 1) & 3, l = (f >> 3) & 31;
        int rest = f >> 8;
        int c = rest & 3, m = (rest >> 2) & 3, t = rest >> 4;
        int b = (m << 4) + ((q & 1) << 3) + (l >> 2);
        int v = (c << 4) + ((q >> 1) << 3) + ((l & 3) << 1) + e;
        g_XF[f] = __float2half(x[(size_t)(b * TIN + t) * V_ + v]);
    }
}

// ----------------------------------------------------------------------------
// GEMM over assigned chunk range [start, end) of the concatenated A0|A1 input.
// W via __ldg (L1-resident), A via __ldcg (L2-only).
// ----------------------------------------------------------------------------
__device__ __forceinline__ void gemm_range(
    const __half* __restrict__ Wb,
    const __half* __restrict__ A0, int n0,
    const __half* __restrict__ A1,
    int start, int end, float acc[4][4], int lane)
{
    int e0 = min(end, n0);
    {
        const __half* a  = A0 + (size_t)start * 256 + lane * 8;
        const __half* wl = Wb + (size_t)start * 512 + lane * 8;
#pragma unroll 4
        for (int c = start; c < e0; ++c) {
            uint4 av = __ldcg((const uint4*)a);
            uint4 w0 = __ldg((const uint4*)wl);
            uint4 w1 = __ldg((const uint4*)(wl + 256));
            mma16816(acc[0], av, w0.x, w0.y);
            mma16816(acc[1], av, w0.z, w0.w);
            mma16816(acc[2], av, w1.x, w1.y);
            mma16816(acc[3], av, w1.z, w1.w);
            a += 256; wl += 512;
        }
    }
    int s1 = max(start, n0);
    {
        const __half* a  = A1 + (size_t)(s1 - n0) * 256 + lane * 8;
        const __half* wl = Wb + (size_t)s1 * 512 + lane * 8;
#pragma unroll 4
        for (int c = s1; c < end; ++c) {
            uint4 av = __ldcg((const uint4*)a);
            uint4 w0 = __ldg((const uint4*)wl);
            uint4 w1 = __ldg((const uint4*)(wl + 256));
            mma16816(acc[0], av, w0.x, w0.y);
            mma16816(acc[1], av, w0.z, w0.w);
            mma16816(acc[2], av, w1.x, w1.y);
            mma16816(acc[3], av, w1.z, w1.w);
            a += 256; wl += 512;
        }
    }
}

// ----------------------------------------------------------------------------
// one LSTM cell phase: K split across warp pairs (w, w+4); kh=1 writes partials
// to smem, kh=0 reduces + runs the cell nonlinearity + writes h (frag order).
// ----------------------------------------------------------------------------
__device__ __forceinline__ void cell_phase(
    const __half* __restrict__ Wb,
    const __half* __restrict__ A0, int n0,
    const __half* __restrict__ A1, int n1,
    const float*  __restrict__ bias,
    float* cr, __half* __restrict__ hout,
    float* __restrict__ red,
    int ct, int w, int kh, int m, int lane)
{
    float acc[4][4];
#pragma unroll
    for (int i = 0; i < 4; ++i)
#pragma unroll
        for (int k = 0; k < 4; ++k) acc[i][k] = 0.0f;

    const int total = n0 + n1;
    const int h = (total + 1) >> 1;
    gemm_range(Wb, A0, n0, A1, kh ? h : 0, kh ? total : h, acc, lane);

    if (kh) {
        float* dst = red + (size_t)m * 512 + lane * 16;
#pragma unroll
        for (int i = 0; i < 4; ++i)
#pragma unroll
            for (int k = 0; k < 4; ++k) dst[i * 4 + k] = acc[i][k];
    }
    __syncthreads();
    if (kh) return;

    const float* src = red + (size_t)m * 512 + lane * 16;
#pragma unroll
    for (int i = 0; i < 4; ++i)
#pragma unroll
        for (int k = 0; k < 4; ++k) acc[i][k] += src[i * 4 + k];

    const bool hi = (lane & 1);
#pragma unroll
    for (int nt = 0; nt < 4; ++nt) {
        float d0 = acc[nt][0], d1 = acc[nt][1], d2 = acc[nt][2], d3 = acc[nt][3];
        int jl = 2 * nt + ((lane & 3) >> 1);
        int j  = ct * 8 + jl;
        int g0 = (lane & 1) * 2;
        float bv0 = __ldg(bias + g0 * 1024 + j);
        float bv1 = __ldg(bias + (g0 + 1) * 1024 + j);
        d0 += bv0; d1 += bv1; d2 += bv0; d3 += bv1;

        float sA = hi ? d0 : d2;
        float sB = hi ? d1 : d3;
        float rA = __shfl_xor_sync(0xffffffffu, sA, 1);
        float rB = __shfl_xor_sync(0xffffffffu, sB, 1);
        float gi = hi ? rA : d0;
        float gf = hi ? rB : d1;
        float gc = hi ? d2 : rA;
        float go = hi ? d3 : rB;

        float cn = sigm(gf) * cr[nt] + sigm(gi) * tanhf(gc);
        cr[nt] = cn;
        float hv = sigm(go) * tanhf(cn);

        int b = m * 16 + (lane >> 2) + (hi ? 8 : 0);
        int ldst = ((b & 7) << 2) + ((j & 7) >> 1);
        int qq = (hi ? 1 : 0) + ((j & 8) ? 2 : 0);
        hout[(size_t)((b >> 4) * 64 + (j >> 4)) * 256 + ldst * 8 + qq * 2 + (j & 1)] =
            __float2half(hv);
    }
}

// ----------------------------------------------------------------------------
// main persistent kernel
// ----------------------------------------------------------------------------
__global__ void __launch_bounds__(NTHR, 1)
rnn_main_kernel(const float* __restrict__ b0, const float* __restrict__ b1,
                const float* __restrict__ bf, float* __restrict__ out)
{
    const int ct   = blockIdx.x;
    const int tid  = threadIdx.x;
    const int w    = tid >> 5;
    const int lane = tid & 31;
    const int m    = w & 3;
    const int kh   = w >> 2;

    float c0r[4] = {0.f, 0.f, 0.f, 0.f};
    float c1r[4] = {0.f, 0.f, 0.f, 0.f};

    const __half* Wb0 = g_W0f + (size_t)ct * 68 * 512;
    const __half* Wb1 = g_W1f + (size_t)ct * 128 * 512;

    __shared__ float red[2048];   // 8 KB: cell k-reduce (4x512) / projection (7x256)

    for (int s = 0; s < TIN + TOUT; ++s) {
        const int p   = s & 1;
        const bool dec = (s >= TIN);

        // ---- layer 0: input = [x_t | h0_old] ----
        const __half* a0base;
        if (!dec)            a0base = g_XF + (size_t)(s * 4 + m) * 4 * 256;
        else if (s == TIN)   a0base = g_XF + (size_t)(255 * 4 + m) * 4 * 256;
        else                 a0base = g_INPF + (size_t)m * 4 * 256;
        const __half* h0old = g_H0F + (size_t)(p * 4 + m) * 16384;
        __half* h0out = g_H0F + (size_t)(1 - p) * 65536;
        cell_phase(Wb0, a0base, 4, h0old, (s > 0) ? 64 : 0, b0, c0r, h0out,
                   red, ct, w, kh, m, lane);
        grid_sync();

        // ---- layer 1: input = [h0_new | h1_old] ----
        const __half* h0new = g_H0F + (size_t)((1 - p) * 4 + m) * 16384;
        const __half* h1old = g_H1F + (size_t)(p * 4 + m) * 16384;
        __half* h1out = g_H1F + (size_t)(1 - p) * 65536;
        cell_phase(Wb1, h0new, 64, h1old, (s > 0) ? 64 : 0, b1, c1r, h1out,
                   red, ct, w, kh, m, lane);
        grid_sync();

        // ---- decoder projection: out = h1 @ Wf^T + bf ----
        if (dec) {
            if (ct < 16) {
                const int mm = ct & 3, vg = ct >> 2;
                // warp w handles K-chunks [w*8, w*8+8) of 64
                const __half* A  = g_H1F + (size_t)((1 - p) * 4 + mm) * 16384
                                   + (size_t)(w * 8) * 256 + lane * 8;
                const __half* Wp = g_Wff + (size_t)(vg * 64 + w * 8) * 256 + lane * 8;
                float pacc[8];
#pragma unroll
                for (int k = 0; k < 8; ++k) pacc[k] = 0.0f;
#pragma unroll
                for (int cc = 0; cc < 8; ++cc) {
                    uint4 av = __ldcg((const uint4*)(A  + (size_t)cc * 256));
                    uint4 wv = __ldg ((const uint4*)(Wp + (size_t)cc * 256));
                    mma16816(pacc + 0, av, wv.x, wv.y);
                    mma16816(pacc + 4, av, wv.z, wv.w);
                }
                if (w > 0) {
                    float* dst = red + (size_t)(w - 1) * 256 + lane * 8;
#pragma unroll
                    for (int k = 0; k < 8; ++k) dst[k] = pacc[k];
                }
                __syncthreads();
                if (w == 0) {
                    float fsum[8];
#pragma unroll
                    for (int k = 0; k < 8; ++k) fsum[k] = pacc[k];
#pragma unroll
                    for (int ww = 1; ww < 8; ++ww) {
                        const float* src = red + (size_t)(ww - 1) * 256 + lane * 8;
#pragma unroll
                        for (int k = 0; k < 8; ++k) fsum[k] += src[k];
                    }
                    const int tdec = s - TIN;
#pragma unroll
                    for (int nt = 0; nt < 2; ++nt)
#pragma unroll
                        for (int rr = 0; rr < 2; ++rr)
#pragma unroll
                            for (int e2 = 0; e2 < 2; ++e2) {
                                int b = mm * 16 + (lane >> 2) + rr * 8;
                                int v = vg * 16 + nt * 8 + ((lane & 3) << 1) + e2;
                                float val = fsum[nt * 4 + rr * 2 + e2] + __ldg(bf + v);
                                out[(size_t)(b * TOUT + tdec) * V_ + v] = val;
                                g_INPF[(size_t)((b >> 4) * 4 + (v >> 4)) * 256
                                       + (((b & 7) << 2) + ((v & 7) >> 1)) * 8
                                       + (rr + ((v & 8) ? 2 : 0)) * 2 + (v & 1)] =
                                    __float2half(val);
                            }
                }
            }
            grid_sync();
        }
    }
}

// ----------------------------------------------------------------------------
extern "C" void kernel_launch(void* const* d_in, const int* in_sizes, int n_in,
                              void* d_out, int out_size) {
    const float* x  = (const float*)d_in[0];
    const float* W0 = (const float*)d_in[1];
    const float* b0 = (const float*)d_in[2];
    const float* W1 = (const float*)d_in[3];
    const float* b1 = (const float*)d_in[4];
    const float* Wf = (const float*)d_in[5];
    const float* bf = (const float*)d_in[6];
    float* out = (float*)d_out;

    prep_w0_kernel<<<2048, 256>>>(W0);
    prep_w1_kernel<<<4096, 256>>>(W1);
    prep_wf_kernel<<<64, 256>>>(Wf);
    prep_x_kernel<<<1024, 256>>>(x);
    rnn_main_kernel<<<NCTA, NTHR>>>(b0, b1, bf, out);
}

// round 6
// speedup vs baseline: 1.6300x; 1.1544x over previous
#include <cuda_runtime.h>
#include <cuda_fp16.h>
#include <math.h>

#define B_    64
#define TIN   256
#define V_    64
#define H_    1024
#define TOUT  32
#define NCTA  128
#define NTHR  256

__device__ __align__(16) __half g_W0f[4456448];
__device__ __align__(16) __half g_W1f[8388608];
__device__ __align__(16) __half g_Wff[65536];
__device__ __align__(16) __half g_XF [1048576];
__device__ __align__(16) __half g_H0F[131072];
__device__ __align__(16) __half g_H1F[131072];
__device__ __align__(16) __half g_INPF[4096];

__device__ unsigned g_bar_count = 0;
__device__ unsigned g_bar_gen   = 0;

__device__ __forceinline__ void mma16816(float* d, const uint4& a,
                                         unsigned b0, unsigned b1) {
    asm volatile(
        "mma.sync.aligned.m16n8k16.row.col.f32.f16.f16.f32 "
        "{%0,%1,%2,%3}, {%4,%5,%6,%7}, {%8,%9}, {%0,%1,%2,%3};\n"
        : "+f"(d[0]), "+f"(d[1]), "+f"(d[2]), "+f"(d[3])
        : "r"(a.x), "r"(a.y), "r"(a.z), "r"(a.w), "r"(b0), "r"(b1));
}

__device__ __forceinline__ float sigm(float x) { return 1.0f / (1.0f + __expf(-x)); }

__device__ __forceinline__ void grid_sync() {
    __syncthreads();
    if (threadIdx.x == 0) {
        unsigned gen;
        asm volatile("ld.acquire.gpu.u32 %0, [%1];" : "=r"(gen) : "l"(&g_bar_gen) : "memory");
        __threadfence();
        unsigned t = atomicAdd(&g_bar_count, 1u);
        if (t == gridDim.x - 1) {
            g_bar_count = 0;
            asm volatile("st.release.gpu.u32 [%0], %1;" :: "l"(&g_bar_gen), "r"(gen + 1u) : "memory");
        } else {
            unsigned cur;
            do {
                asm volatile("ld.acquire.gpu.u32 %0, [%1];" : "=r"(cur) : "l"(&g_bar_gen) : "memory");
            } while (cur == gen);
        }
        __threadfence();
    }
    __syncthreads();
}

// ---- prep kernels (layouts verified in R2/R3) ----
__global__ void prep_w0_kernel(const float* __restrict__ W) {
    const int total = 4456448, K = 1088, nchunk = 68;
    for (int f = blockIdx.x * blockDim.x + threadIdx.x; f < total; f += gridDim.x * blockDim.x) {
        int e = f & 1, q = (f >> 1) & 3, l = (f >> 3) & 31, ng = (f >> 8) & 1;
        int rest = f >> 9;
        int c = rest % nchunk, ct = rest / nchunk;
        int n = (ng << 4) + ((q >> 1) << 3) + (l >> 2);
        int k = (c << 4) + ((q & 1) << 3) + ((l & 3) << 1) + e;
        int j = (ct << 3) + (n >> 2);
        g_W0f[f] = __float2half(W[(size_t)((n & 3) * 1024 + j) * K + k]);
    }
}
__global__ void prep_w1_kernel(const float* __restrict__ W) {
    const int total = 8388608, K = 2048;
    for (int f = blockIdx.x * blockDim.x + threadIdx.x; f < total; f += gridDim.x * blockDim.x) {
        int e = f & 1, q = (f >> 1) & 3, l = (f >> 3) & 31, ng = (f >> 8) & 1;
        int rest = f >> 9;
        int c = rest & 127, ct = rest >> 7;
        int n = (ng << 4) + ((q >> 1) << 3) + (l >> 2);
        int k = (c << 4) + ((q & 1) << 3) + ((l & 3) << 1) + e;
        int j = (ct << 3) + (n >> 2);
        g_W1f[f] = __float2half(W[(size_t)((n & 3) * 1024 + j) * K + k]);
    }
}
__global__ void prep_wf_kernel(const float* __restrict__ Wf) {
    const int total = 65536;
    for (int f = blockIdx.x * blockDim.x + threadIdx.x; f < total; f += gridDim.x * blockDim.x) {
        int e = f & 1, q = (f >> 1) & 3, l = (f >> 3) & 31;
        int rest = f >> 8;
        int c = rest & 63, vg = rest >> 6;
        int v = (vg << 4) + ((q >> 1) << 3) + (l >> 2);
        int j = (c << 4) + ((q & 1) << 3) + ((l & 3) << 1) + e;
        g_Wff[f] = __float2half(Wf[(size_t)v * 1024 + j]);
    }
}
__global__ void prep_x_kernel(const float* __restrict__ x) {
    const int total = 1048576;
    for (int f = blockIdx.x * blockDim.x + threadIdx.x; f < total; f += gridDim.x * blockDim.x) {
        int e = f & 1, q = (f >> 1) & 3, l = (f >> 3) & 31;
        int rest = f >> 8;
        int c = rest & 3, m = (rest >> 2) & 3, t = rest >> 4;
        int b = (m << 4) + ((q & 1) << 3) + (l >> 2);
        int v = (c << 4) + ((q >> 1) << 3) + ((l & 3) << 1) + e;
        g_XF[f] = __float2half(x[(size_t)(b * TIN + t) * V_ + v]);
    }
}

// ---- GEMM over chunk range of concatenated A0|A1 ----
__device__ __forceinline__ void gemm_range(
    const __half* __restrict__ Wb,
    const __half* __restrict__ A0, int n0,
    const __half* __restrict__ A1,
    int start, int end, float acc[4][4], int lane)
{
    int e0 = min(end, n0);
    {
        const __half* a  = A0 + (size_t)start * 256 + lane * 8;
        const __half* wl = Wb + (size_t)start * 512 + lane * 8;
#pragma unroll 4
        for (int c = start; c < e0; ++c) {
            uint4 av = __ldcg((const uint4*)a);
            uint4 w0 = __ldg((const uint4*)wl);
            uint4 w1 = __ldg((const uint4*)(wl + 256));
            mma16816(acc[0], av, w0.x, w0.y);
            mma16816(acc[1], av, w0.z, w0.w);
            mma16816(acc[2], av, w1.x, w1.y);
            mma16816(acc[3], av, w1.z, w1.w);
            a += 256; wl += 512;
        }
    }
    int s1 = max(start, n0);
    {
        const __half* a  = A1 + (size_t)(s1 - n0) * 256 + lane * 8;
        const __half* wl = Wb + (size_t)s1 * 512 + lane * 8;
#pragma unroll 4
        for (int c = s1; c < end; ++c) {
            uint4 av = __ldcg((const uint4*)a);
            uint4 w0 = __ldg((const uint4*)wl);
            uint4 w1 = __ldg((const uint4*)(wl + 256));
            mma16816(acc[0], av, w0.x, w0.y);
            mma16816(acc[1], av, w0.z, w0.w);
            mma16816(acc[2], av, w1.x, w1.y);
            mma16816(acc[3], av, w1.z, w1.w);
            a += 256; wl += 512;
        }
    }
}

// ---- one LSTM cell phase (kh-split + smem reduce + epilogue) ----
__device__ __forceinline__ void cell_phase(
    const __half* __restrict__ Wb,
    const __half* __restrict__ A0, int n0,
    const __half* __restrict__ A1, int n1,
    const float*  __restrict__ bias,
    float* cr, __half* __restrict__ hout,
    float* __restrict__ red,
    int ct, int kh, int m, int lane)
{
    float acc[4][4];
#pragma unroll
    for (int i = 0; i < 4; ++i)
#pragma unroll
        for (int k = 0; k < 4; ++k) acc[i][k] = 0.0f;

    const int total = n0 + n1;
    const int h = (total + 1) >> 1;
    gemm_range(Wb, A0, n0, A1, kh ? h : 0, kh ? total : h, acc, lane);

    if (kh) {
        float* dst = red + (size_t)m * 512 + lane * 16;
#pragma unroll
        for (int i = 0; i < 4; ++i)
#pragma unroll
            for (int k = 0; k < 4; ++k) dst[i * 4 + k] = acc[i][k];
    }
    __syncthreads();
    if (kh) return;

    const float* src = red + (size_t)m * 512 + lane * 16;
#pragma unroll
    for (int i = 0; i < 4; ++i)
#pragma unroll
        for (int k = 0; k < 4; ++k) acc[i][k] += src[i * 4 + k];

    const bool hi = (lane & 1);
#pragma unroll
    for (int nt = 0; nt < 4; ++nt) {
        float d0 = acc[nt][0], d1 = acc[nt][1], d2 = acc[nt][2], d3 = acc[nt][3];
        int j  = ct * 8 + 2 * nt + ((lane & 3) >> 1);
        int g0 = (lane & 1) * 2;
        float bv0 = __ldg(bias + g0 * 1024 + j);
        float bv1 = __ldg(bias + (g0 + 1) * 1024 + j);
        d0 += bv0; d1 += bv1; d2 += bv0; d3 += bv1;

        float sA = hi ? d0 : d2;
        float sB = hi ? d1 : d3;
        float rA = __shfl_xor_sync(0xffffffffu, sA, 1);
        float rB = __shfl_xor_sync(0xffffffffu, sB, 1);
        float gi = hi ? rA : d0;
        float gf = hi ? rB : d1;
        float gc = hi ? d2 : rA;
        float go = hi ? d3 : rB;

        float cn = sigm(gf) * cr[nt] + sigm(gi) * tanhf(gc);
        cr[nt] = cn;
        float hv = sigm(go) * tanhf(cn);

        int b = m * 16 + (lane >> 2) + (hi ? 8 : 0);
        int ldst = ((b & 7) << 2) + ((j & 7) >> 1);
        int qq = (hi ? 1 : 0) + ((j & 8) ? 2 : 0);
        hout[(size_t)((b >> 4) * 64 + (j >> 4)) * 256 + ldst * 8 + qq * 2 + (j & 1)] =
            __float2half(hv);
    }
}

// ---- main persistent kernel: skewed L0/L1 pipeline (1 sync per encoder phase) ----
__global__ void __launch_bounds__(NTHR, 1)
rnn_main_kernel(const float* __restrict__ b0, const float* __restrict__ b1,
                const float* __restrict__ bf, float* __restrict__ out)
{
    const int ct   = blockIdx.x;
    const int tid  = threadIdx.x;
    const int w    = tid >> 5;
    const int lane = tid & 31;
    const int m    = w & 3;
    const int kh   = w >> 2;

    float c0r[4] = {0.f, 0.f, 0.f, 0.f};
    float c1r[4] = {0.f, 0.f, 0.f, 0.f};

    const __half* Wb0 = g_W0f + (size_t)ct * 68 * 512;
    const __half* Wb1 = g_W1f + (size_t)ct * 128 * 512;

    __shared__ float red[4096];   // 16 KB: [0,2048) L0/proj, [2048,4096) L1

    // Buffer convention: h0(t) lives in g_H0F buffer (t&1); h1(t) in g_H1F (t&1).
    // Encoder phases p=0..256: compute L0(p) (p<256) and L1(p-1) (p>=1); ONE sync.
    for (int p = 0; p <= 256; ++p) {
        if (p < 256) {
            const __half* a0    = g_XF + (size_t)(p * 4 + m) * 1024;
            const __half* h0old = g_H0F + (size_t)((((p - 1) & 1)) * 4 + m) * 16384;
            __half* h0out = g_H0F + (size_t)(p & 1) * 65536;
            cell_phase(Wb0, a0, 4, h0old, p ? 64 : 0, b0, c0r, h0out,
                       red, ct, kh, m, lane);
        }
        if (p >= 1) {
            const int s1 = p - 1;
            const __half* h0new = g_H0F + (size_t)((s1 & 1) * 4 + m) * 16384;
            const __half* h1old = g_H1F + (size_t)((((s1 - 1) & 1)) * 4 + m) * 16384;
            __half* h1out = g_H1F + (size_t)(s1 & 1) * 65536;
            cell_phase(Wb1, h0new, 64, h1old, s1 ? 64 : 0, b1, c1r, h1out,
                       red + 2048, ct, kh, m, lane);
        }
        grid_sync();
    }

    // Decoder steps s=256..287: L0 | sync | L1 | sync | proj | sync
    for (int s = 256; s < 288; ++s) {
        const __half* a0 = (s == 256) ? g_XF + (size_t)(255 * 4 + m) * 1024
                                      : g_INPF + (size_t)m * 1024;
        cell_phase(Wb0, a0, 4,
                   g_H0F + (size_t)(((s - 1) & 1) * 4 + m) * 16384, 64, b0, c0r,
                   g_H0F + (size_t)(s & 1) * 65536, red, ct, kh, m, lane);
        grid_sync();
        cell_phase(Wb1, g_H0F + (size_t)((s & 1) * 4 + m) * 16384, 64,
                   g_H1F + (size_t)(((s - 1) & 1) * 4 + m) * 16384, 64, b1, c1r,
                   g_H1F + (size_t)(s & 1) * 65536, red + 2048, ct, kh, m, lane);
        grid_sync();

        if (ct < 16) {
            const int mm = ct & 3, vg = ct >> 2;
            const __half* A  = g_H1F + (size_t)((s & 1) * 4 + mm) * 16384
                               + (size_t)(w * 8) * 256 + lane * 8;
            const __half* Wp = g_Wff + (size_t)(vg * 64 + w * 8) * 256 + lane * 8;
            float pacc[8];
#pragma unroll
            for (int k = 0; k < 8; ++k) pacc[k] = 0.0f;
#pragma unroll
            for (int cc = 0; cc < 8; ++cc) {
                uint4 av = __ldcg((const uint4*)(A  + (size_t)cc * 256));
                uint4 wv = __ldg ((const uint4*)(Wp + (size_t)cc * 256));
                mma16816(pacc + 0, av, wv.x, wv.y);
                mma16816(pacc + 4, av, wv.z, wv.w);
            }
            if (w > 0) {
                float* dst = red + (size_t)(w - 1) * 256 + lane * 8;
#pragma unroll
                for (int k = 0; k < 8; ++k) dst[k] = pacc[k];
            }
            __syncthreads();
            if (w == 0) {
                float fsum[8];
#pragma unroll
                for (int k = 0; k < 8; ++k) fsum[k] = pacc[k];
#pragma unroll
                for (int ww = 1; ww < 8; ++ww) {
                    const float* src = red + (size_t)(ww - 1) * 256 + lane * 8;
#pragma unroll
                    for (int k = 0; k < 8; ++k) fsum[k] += src[k];
                }
                const int tdec = s - TIN;
#pragma unroll
                for (int nt = 0; nt < 2; ++nt)
#pragma unroll
                    for (int rr = 0; rr < 2; ++rr)
#pragma unroll
                        for (int e2 = 0; e2 < 2; ++e2) {
                            int b = mm * 16 + (lane >> 2) + rr * 8;
                            int v = vg * 16 + nt * 8 + ((lane & 3) << 1) + e2;
                            float val = fsum[nt * 4 + rr * 2 + e2] + __ldg(bf + v);
                            out[(size_t)(b * TOUT + tdec) * V_ + v] = val;
                            g_INPF[(size_t)((b >> 4) * 4 + (v >> 4)) * 256
                                   + (((b & 7) << 2) + ((v & 7) >> 1)) * 8
                                   + (rr + ((v & 8) ? 2 : 0)) * 2 + (v & 1)] =
                                __float2half(val);
                        }
            }
        } else {
            __syncthreads();
        }
        grid_sync();
    }
}

extern "C" void kernel_launch(void* const* d_in, const int* in_sizes, int n_in,
                              void* d_out, int out_size) {
    const float* x  = (const float*)d_in[0];
    const float* W0 = (const float*)d_in[1];
    const float* b0 = (const float*)d_in[2];
    const float* W1 = (const float*)d_in[3];
    const float* b1 = (const float*)d_in[4];
    const float* Wf = (const float*)d_in[5];
    const float* bf = (const float*)d_in[6];
    float* out = (float*)d_out;

    prep_w0_kernel<<<2048, 256>>>(W0);
    prep_w1_kernel<<<4096, 256>>>(W1);
    prep_wf_kernel<<<64, 256>>>(Wf);
    prep_x_kernel<<<1024, 256>>>(x);
    rnn_main_kernel<<<NCTA, NTHR>>>(b0, b1, bf, out);
}

// round 8
// speedup vs baseline: 1.7381x; 1.0663x over previous
#include <cuda_runtime.h>
#include <cuda_fp16.h>
#include <math.h>

#define B_    64
#define TIN   256
#define V_    64
#define H_    1024
#define TOUT  32
#define NCTA  128
#define NTHR  512   // 16 warps: m = w&3 (batch tile), kseg = w>>2 (K quarter)

__device__ __align__(16) __half g_W0f[4456448];
__device__ __align__(16) __half g_W1f[8388608];
__device__ __align__(16) __half g_Wff[65536];
__device__ __align__(16) __half g_XF [1048576];
__device__ __align__(16) __half g_H0F[131072];
__device__ __align__(16) __half g_H1F[131072];
__device__ __align__(16) __half g_INPF[4096];

__device__ unsigned g_bar_count = 0;
__device__ unsigned g_bar_gen   = 0;

__device__ __forceinline__ void mma16816(float* d, const uint4& a,
                                         unsigned b0, unsigned b1) {
    asm volatile(
        "mma.sync.aligned.m16n8k16.row.col.f32.f16.f16.f32 "
        "{%0,%1,%2,%3}, {%4,%5,%6,%7}, {%8,%9}, {%0,%1,%2,%3};\n"
        : "+f"(d[0]), "+f"(d[1]), "+f"(d[2]), "+f"(d[3])
        : "r"(a.x), "r"(a.y), "r"(a.z), "r"(a.w), "r"(b0), "r"(b1));
}

__device__ __forceinline__ float sigm(float x) { return 1.0f / (1.0f + __expf(-x)); }

__device__ __forceinline__ void grid_sync() {
    __syncthreads();
    if (threadIdx.x == 0) {
        unsigned gen;
        asm volatile("ld.acquire.gpu.u32 %0, [%1];" : "=r"(gen) : "l"(&g_bar_gen) : "memory");
        __threadfence();
        unsigned t = atomicAdd(&g_bar_count, 1u);
        if (t == gridDim.x - 1) {
            g_bar_count = 0;
            asm volatile("st.release.gpu.u32 [%0], %1;" :: "l"(&g_bar_gen), "r"(gen + 1u) : "memory");
        } else {
            unsigned cur;
            do {
                asm volatile("ld.acquire.gpu.u32 %0, [%1];" : "=r"(cur) : "l"(&g_bar_gen) : "memory");
            } while (cur == gen);
        }
        __threadfence();
    }
    __syncthreads();
}

// ---- single merged prep kernel (fragment-order layouts verified R2-R6) ----
#define PW0 4456448
#define PW1 (PW0 + 8388608)
#define PWF (PW1 + 65536)
#define PX  (PWF + 1048576)
__global__ void prep_all(const float* __restrict__ x,  const float* __restrict__ W0,
                         const float* __restrict__ W1, const float* __restrict__ Wf) {
    for (int f = blockIdx.x * blockDim.x + threadIdx.x; f < PX; f += gridDim.x * blockDim.x) {
        if (f < PW0) {
            const int K = 1088, nchunk = 68;
            int e = f & 1, q = (f >> 1) & 3, l = (f >> 3) & 31, ng = (f >> 8) & 1;
            int rest = f >> 9;
            int c = rest % nchunk, ct = rest / nchunk;
            int n = (ng << 4) + ((q >> 1) << 3) + (l >> 2);
            int k = (c << 4) + ((q & 1) << 3) + ((l & 3) << 1) + e;
            int j = (ct << 3) + (n >> 2);
            g_W0f[f] = __float2half(W0[(size_t)((n & 3) * 1024 + j) * K + k]);
        } else if (f < PW1) {
            int f2 = f - PW0;
            const int K = 2048;
            int e = f2 & 1, q = (f2 >> 1) & 3, l = (f2 >> 3) & 31, ng = (f2 >> 8) & 1;
            int rest = f2 >> 9;
            int c = rest & 127, ct = rest >> 7;
            int n = (ng << 4) + ((q >> 1) << 3) + (l >> 2);
            int k = (c << 4) + ((q & 1) << 3) + ((l & 3) << 1) + e;
            int j = (ct << 3) + (n >> 2);
            g_W1f[f2] = __float2half(W1[(size_t)((n & 3) * 1024 + j) * K + k]);
        } else if (f < PWF) {
            int f3 = f - PW1;
            int e = f3 & 1, q = (f3 >> 1) & 3, l = (f3 >> 3) & 31;
            int rest = f3 >> 8;
            int c = rest & 63, vg = rest >> 6;
            int v = (vg << 4) + ((q >> 1) << 3) + (l >> 2);
            int j = (c << 4) + ((q & 1) << 3) + ((l & 3) << 1) + e;
            g_Wff[f3] = __float2half(Wf[(size_t)v * 1024 + j]);
        } else {
            int f4 = f - PWF;
            int e = f4 & 1, q = (f4 >> 1) & 3, l = (f4 >> 3) & 31;
            int rest = f4 >> 8;
            int c = rest & 3, m = (rest >> 2) & 3, t = rest >> 4;
            int b = (m << 4) + ((q & 1) << 3) + (l >> 2);
            int v = (c << 4) + ((q >> 1) << 3) + ((l & 3) << 1) + e;
            g_XF[f4] = __float2half(x[(size_t)(b * TIN + t) * V_ + v]);
        }
    }
}

// ---- GEMM over chunk range of concatenated A0|A1 ----
__device__ __forceinline__ void gemm_range(
    const __half* __restrict__ Wb,
    const __half* __restrict__ A0, int n0,
    const __half* __restrict__ A1,
    int start, int end, float acc[4][4], int lane)
{
    int e0 = min(end, n0);
    {
        const __half* a  = A0 + (size_t)start * 256 + lane * 8;
        const __half* wl = Wb + (size_t)start * 512 + lane * 8;
#pragma unroll 8
        for (int c = start; c < e0; ++c) {
            uint4 av = __ldcg((const uint4*)a);
            uint4 w0 = __ldg((const uint4*)wl);
            uint4 w1 = __ldg((const uint4*)(wl + 256));
            mma16816(acc[0], av, w0.x, w0.y);
            mma16816(acc[1], av, w0.z, w0.w);
            mma16816(acc[2], av, w1.x, w1.y);
            mma16816(acc[3], av, w1.z, w1.w);
            a += 256; wl += 512;
        }
    }
    int s1 = max(start, n0);
    {
        const __half* a  = A1 + (size_t)(s1 - n0) * 256 + lane * 8;
        const __half* wl = Wb + (size_t)s1 * 512 + lane * 8;
#pragma unroll 8
        for (int c = s1; c < end; ++c) {
            uint4 av = __ldcg((const uint4*)a);
            uint4 w0 = __ldg((const uint4*)wl);
            uint4 w1 = __ldg((const uint4*)(wl + 256));
            mma16816(acc[0], av, w0.x, w0.y);
            mma16816(acc[1], av, w0.z, w0.w);
            mma16816(acc[2], av, w1.x, w1.y);
            mma16816(acc[3], av, w1.z, w1.w);
            a += 256; wl += 512;
        }
    }
}

// ---- one LSTM cell phase: K split x4; kseg>0 store partials, kseg=0 reduces
//      3 partials + runs nonlinearity + writes h (frag order). ----
__device__ __forceinline__ void cell_phase(
    const __half* __restrict__ Wb,
    const __half* __restrict__ A0, int n0,
    const __half* __restrict__ A1, int n1,
    const float*  __restrict__ bias,
    float* cr, __half* __restrict__ hout,
    float* __restrict__ red,
    int ct, int kseg, int m, int lane)
{
    float acc[4][4];
#pragma unroll
    for (int i = 0; i < 4; ++i)
#pragma unroll
        for (int k = 0; k < 4; ++k) acc[i][k] = 0.0f;

    const int nc  = n0 + n1;
    const int len = nc >> 2;                    // nc in {4,68,128}: divisible by 4
    gemm_range(Wb, A0, n0, A1, kseg * len, kseg * len + len, acc, lane);

    if (kseg) {
        float* dst = red + (size_t)((kseg - 1) * 4 + m) * 512 + lane * 16;
#pragma unroll
        for (int i = 0; i < 4; ++i)
#pragma unroll
            for (int k = 0; k < 4; ++k) dst[i * 4 + k] = acc[i][k];
    }
    __syncthreads();
    if (kseg) return;

#pragma unroll
    for (int t = 0; t < 3; ++t) {
        const float* src = red + (size_t)(t * 4 + m) * 512 + lane * 16;
#pragma unroll
        for (int i = 0; i < 4; ++i)
#pragma unroll
            for (int k = 0; k < 4; ++k) acc[i][k] += src[i * 4 + k];
    }

    const bool hi = (lane & 1);
#pragma unroll
    for (int nt = 0; nt < 4; ++nt) {
        float d0 = acc[nt][0], d1 = acc[nt][1], d2 = acc[nt][2], d3 = acc[nt][3];
        int j  = ct * 8 + 2 * nt + ((lane & 3) >> 1);
        int g0 = (lane & 1) * 2;
        float bv0 = __ldg(bias + g0 * 1024 + j);
        float bv1 = __ldg(bias + (g0 + 1) * 1024 + j);
        d0 += bv0; d1 += bv1; d2 += bv0; d3 += bv1;

        float sA = hi ? d0 : d2;
        float sB = hi ? d1 : d3;
        float rA = __shfl_xor_sync(0xffffffffu, sA, 1);
        float rB = __shfl_xor_sync(0xffffffffu, sB, 1);
        float gi = hi ? rA : d0;
        float gf = hi ? rB : d1;
        float gc = hi ? d2 : rA;
        float go = hi ? d3 : rB;

        float cn = sigm(gf) * cr[nt] + sigm(gi) * tanhf(gc);
        cr[nt] = cn;
        float hv = sigm(go) * tanhf(cn);

        int b = m * 16 + (lane >> 2) + (hi ? 8 : 0);
        int ldst = ((b & 7) << 2) + ((j & 7) >> 1);
        int qq = (hi ? 1 : 0) + ((j & 8) ? 2 : 0);
        hout[(size_t)((b >> 4) * 64 + (j >> 4)) * 256 + ldst * 8 + qq * 2 + (j & 1)] =
            __float2half(hv);
    }
}

// ---- main persistent kernel: skewed L0/L1 pipeline, 1 sync per encoder phase ----
__global__ void __launch_bounds__(NTHR, 1)
rnn_main_kernel(const float* __restrict__ b0, const float* __restrict__ b1,
                const float* __restrict__ bf, float* __restrict__ out)
{
    const int ct   = blockIdx.x;
    const int tid  = threadIdx.x;
    const int w    = tid >> 5;
    const int lane = tid & 31;
    const int m    = w & 3;
    const int kseg = w >> 2;

    float c0r[4] = {0.f, 0.f, 0.f, 0.f};
    float c1r[4] = {0.f, 0.f, 0.f, 0.f};

    const __half* Wb0 = g_W0f + (size_t)ct * 68 * 512;
    const __half* Wb1 = g_W1f + (size_t)ct * 128 * 512;

    __shared__ float red[12288];   // 48 KB: [0,6144) L0/proj, [6144,12288) L1

    // h0(t) in g_H0F buffer (t&1); h1(t) in g_H1F (t&1).
    for (int p = 0; p <= 256; ++p) {
        if (p < 256) {
            const __half* a0    = g_XF + (size_t)(p * 4 + m) * 1024;
            const __half* h0old = g_H0F + (size_t)((((p - 1) & 1)) * 4 + m) * 16384;
            __half* h0out = g_H0F + (size_t)(p & 1) * 65536;
            cell_phase(Wb0, a0, 4, h0old, p ? 64 : 0, b0, c0r, h0out,
                       red, ct, kseg, m, lane);
        }
        if (p >= 1) {
            const int s1 = p - 1;
            const __half* h0new = g_H0F + (size_t)((s1 & 1) * 4 + m) * 16384;
            const __half* h1old = g_H1F + (size_t)((((s1 - 1) & 1)) * 4 + m) * 16384;
            __half* h1out = g_H1F + (size_t)(s1 & 1) * 65536;
            cell_phase(Wb1, h0new, 64, h1old, s1 ? 64 : 0, b1, c1r, h1out,
                       red + 6144, ct, kseg, m, lane);
        }
        grid_sync();
    }

    // Decoder: L0 | sync | L1 | sync | proj | sync
    for (int s = 256; s < 288; ++s) {
        const __half* a0 = (s == 256) ? g_XF + (size_t)(255 * 4 + m) * 1024
                                      : g_INPF + (size_t)m * 1024;
        cell_phase(Wb0, a0, 4,
                   g_H0F + (size_t)(((s - 1) & 1) * 4 + m) * 16384, 64, b0, c0r,
                   g_H0F + (size_t)(s & 1) * 65536, red, ct, kseg, m, lane);
        grid_sync();
        cell_phase(Wb1, g_H0F + (size_t)((s & 1) * 4 + m) * 16384, 64,
                   g_H1F + (size_t)(((s - 1) & 1) * 4 + m) * 16384, 64, b1, c1r,
                   g_H1F + (size_t)(s & 1) * 65536, red + 6144, ct, kseg, m, lane);
        grid_sync();

        float pacc[8];
        if (ct < 16 && w < 8) {
            const int mm = ct & 3, vg = ct >> 2;
            const __half* A  = g_H1F + (size_t)((s & 1) * 4 + mm) * 16384
                               + (size_t)(w * 8) * 256 + lane * 8;
            const __half* Wp = g_Wff + (size_t)(vg * 64 + w * 8) * 256 + lane * 8;
#pragma unroll
            for (int k = 0; k < 8; ++k) pacc[k] = 0.0f;
#pragma unroll
            for (int cc = 0; cc < 8; ++cc) {
                uint4 av = __ldcg((const uint4*)(A  + (size_t)cc * 256));
                uint4 wv = __ldg ((const uint4*)(Wp + (size_t)cc * 256));
                mma16816(pacc + 0, av, wv.x, wv.y);
                mma16816(pacc + 4, av, wv.z, wv.w);
            }
            if (w > 0) {
                float* dst = red + (size_t)(w - 1) * 256 + lane * 8;
#pragma unroll
                for (int k = 0; k < 8; ++k) dst[k] = pacc[k];
            }
        }
        __syncthreads();
        if (ct < 16 && w == 0) {
            float fsum[8];
#pragma unroll
            for (int k = 0; k < 8; ++k) fsum[k] = pacc[k];
#pragma unroll
            for (int ww = 1; ww < 8; ++ww) {
                const float* src = red + (size_t)(ww - 1) * 256 + lane * 8;
#pragma unroll
                for (int k = 0; k < 8; ++k) fsum[k] += src[k];
            }
            const int mm = ct & 3, vg = ct >> 2;
            const int tdec = s - TIN;
#pragma unroll
            for (int nt = 0; nt < 2; ++nt)
#pragma unroll
                for (int rr = 0; rr < 2; ++rr)
#pragma unroll
                    for (int e2 = 0; e2 < 2; ++e2) {
                        int b = mm * 16 + (lane >> 2) + rr * 8;
                        int v = vg * 16 + nt * 8 + ((lane & 3) << 1) + e2;
                        float val = fsum[nt * 4 + rr * 2 + e2] + __ldg(bf + v);
                        out[(size_t)(b * TOUT + tdec) * V_ + v] = val;
                        g_INPF[(size_t)((b >> 4) * 4 + (v >> 4)) * 256
                               + (((b & 7) << 2) + ((v & 7) >> 1)) * 8
                               + (rr + ((v & 8) ? 2 : 0)) * 2 + (v & 1)] =
                            __float2half(val);
                    }
        }
        grid_sync();
    }
}

extern "C" void kernel_launch(void* const* d_in, const int* in_sizes, int n_in,
                              void* d_out, int out_size) {
    const float* x  = (const float*)d_in[0];
    const float* W0 = (const float*)d_in[1];
    const float* b0 = (const float*)d_in[2];
    const float* W1 = (const float*)d_in[3];
    const float* b1 = (const float*)d_in[4];
    const float* Wf = (const float*)d_in[5];
    const float* bf = (const float*)d_in[6];
    float* out = (float*)d_out;

    prep_all<<<8192, 256>>>(x, W0, W1, Wf);
    rnn_main_kernel<<<NCTA, NTHR>>>(b0, b1, bf, out);
}

// round 10
// speedup vs baseline: 1.9545x; 1.1245x over previous
#include <cuda_runtime.h>
#include <cuda_fp16.h>
#include <math.h>

#define B_    64
#define TIN   256
#define V_    64
#define H_    1024
#define TOUT  32
#define NCTA  128
#define NTHR  512   // 16 warps: m = w&3 (batch tile), kseg = w>>2 (K quarter = epilogue nt)

__device__ __align__(16) __half g_W0f[4456448];
__device__ __align__(16) __half g_W1f[8388608];
__device__ __align__(16) __half g_Wff[65536];
__device__ __align__(16) __half g_XF [1048576];
__device__ __align__(16) __half g_H0F[131072];
__device__ __align__(16) __half g_H1F[131072];
__device__ __align__(16) __half g_INPF[4096];

__device__ unsigned g_bar_count = 0;
__device__ unsigned g_bar_gen   = 0;

__device__ __forceinline__ void mma16816(float* d, const uint4& a,
                                         unsigned b0, unsigned b1) {
    asm volatile(
        "mma.sync.aligned.m16n8k16.row.col.f32.f16.f16.f32 "
        "{%0,%1,%2,%3}, {%4,%5,%6,%7}, {%8,%9}, {%0,%1,%2,%3};\n"
        : "+f"(d[0]), "+f"(d[1]), "+f"(d[2]), "+f"(d[3])
        : "r"(a.x), "r"(a.y), "r"(a.z), "r"(a.w), "r"(b0), "r"(b1));
}

// fast activations: MUFU ex2 + MUFU rcp (rel err ~1e-6, far below fp16 noise)
__device__ __forceinline__ float sigm(float x) {
    return __fdividef(1.0f, 1.0f + __expf(-x));
}
__device__ __forceinline__ float tanh_f(float x) {
    return __fdividef(2.0f, 1.0f + __expf(-2.0f * x)) - 1.0f;
}

__device__ __forceinline__ void grid_sync() {
    __syncthreads();
    if (threadIdx.x == 0) {
        unsigned gen;
        asm volatile("ld.acquire.gpu.u32 %0, [%1];" : "=r"(gen) : "l"(&g_bar_gen) : "memory");
        __threadfence();
        unsigned t = atomicAdd(&g_bar_count, 1u);
        if (t == gridDim.x - 1) {
            g_bar_count = 0;
            asm volatile("st.release.gpu.u32 [%0], %1;" :: "l"(&g_bar_gen), "r"(gen + 1u) : "memory");
        } else {
            unsigned cur;
            do {
                asm volatile("ld.acquire.gpu.u32 %0, [%1];" : "=r"(cur) : "l"(&g_bar_gen) : "memory");
            } while (cur == gen);
        }
        __threadfence();
    }
    __syncthreads();
}

// ---- single merged prep kernel (fragment-order layouts verified R2-R8) ----
#define PW0 4456448
#define PW1 (PW0 + 8388608)
#define PWF (PW1 + 65536)
#define PX  (PWF + 1048576)
__global__ void prep_all(const float* __restrict__ x,  const float* __restrict__ W0,
                         const float* __restrict__ W1, const float* __restrict__ Wf) {
    for (int f = blockIdx.x * blockDim.x + threadIdx.x; f < PX; f += gridDim.x * blockDim.x) {
        if (f < PW0) {
            const int K = 1088, nchunk = 68;
            int e = f & 1, q = (f >> 1) & 3, l = (f >> 3) & 31, ng = (f >> 8) & 1;
            int rest = f >> 9;
            int c = rest % nchunk, ct = rest / nchunk;
            int n = (ng << 4) + ((q >> 1) << 3) + (l >> 2);
            int k = (c << 4) + ((q & 1) << 3) + ((l & 3) << 1) + e;
            int j = (ct << 3) + (n >> 2);
            g_W0f[f] = __float2half(W0[(size_t)((n & 3) * 1024 + j) * K + k]);
        } else if (f < PW1) {
            int f2 = f - PW0;
            const int K = 2048;
            int e = f2 & 1, q = (f2 >> 1) & 3, l = (f2 >> 3) & 31, ng = (f2 >> 8) & 1;
            int rest = f2 >> 9;
            int c = rest & 127, ct = rest >> 7;
            int n = (ng << 4) + ((q >> 1) << 3) + (l >> 2);
            int k = (c << 4) + ((q & 1) << 3) + ((l & 3) << 1) + e;
            int j = (ct << 3) + (n >> 2);
            g_W1f[f2] = __float2half(W1[(size_t)((n & 3) * 1024 + j) * K + k]);
        } else if (f < PWF) {
            int f3 = f - PW1;
            int e = f3 & 1, q = (f3 >> 1) & 3, l = (f3 >> 3) & 31;
            int rest = f3 >> 8;
            int c = rest & 63, vg = rest >> 6;
            int v = (vg << 4) + ((q >> 1) << 3) + (l >> 2);
            int j = (c << 4) + ((q & 1) << 3) + ((l & 3) << 1) + e;
            g_Wff[f3] = __float2half(Wf[(size_t)v * 1024 + j]);
        } else {
            int f4 = f - PWF;
            int e = f4 & 1, q = (f4 >> 1) & 3, l = (f4 >> 3) & 31;
            int rest = f4 >> 8;
            int c = rest & 3, m = (rest >> 2) & 3, t = rest >> 4;
            int b = (m << 4) + ((q & 1) << 3) + (l >> 2);
            int v = (c << 4) + ((q >> 1) << 3) + ((l & 3) << 1) + e;
            g_XF[f4] = __float2half(x[(size_t)(b * TIN + t) * V_ + v]);
        }
    }
}

// ---- GEMM over chunk range of concatenated A0|A1 ----
__device__ __forceinline__ void gemm_range(
    const __half* __restrict__ Wb,
    const __half* __restrict__ A0, int n0,
    const __half* __restrict__ A1,
    int start, int end, float acc[4][4], int lane)
{
    int e0 = min(end, n0);
    {
        const __half* a  = A0 + (size_t)start * 256 + lane * 8;
        const __half* wl = Wb + (size_t)start * 512 + lane * 8;
#pragma unroll 8
        for (int c = start; c < e0; ++c) {
            uint4 av = __ldcg((const uint4*)a);
            uint4 w0 = __ldg((const uint4*)wl);
            uint4 w1 = __ldg((const uint4*)(wl + 256));
            mma16816(acc[0], av, w0.x, w0.y);
            mma16816(acc[1], av, w0.z, w0.w);
            mma16816(acc[2], av, w1.x, w1.y);
            mma16816(acc[3], av, w1.z, w1.w);
            a += 256; wl += 512;
        }
    }
    int s1 = max(start, n0);
    {
        const __half* a  = A1 + (size_t)(s1 - n0) * 256 + lane * 8;
        const __half* wl = Wb + (size_t)s1 * 512 + lane * 8;
#pragma unroll 8
        for (int c = s1; c < end; ++c) {
            uint4 av = __ldcg((const uint4*)a);
            uint4 w0 = __ldg((const uint4*)wl);
            uint4 w1 = __ldg((const uint4*)(wl + 256));
            mma16816(acc[0], av, w0.x, w0.y);
            mma16816(acc[1], av, w0.z, w0.w);
            mma16816(acc[2], av, w1.x, w1.y);
            mma16816(acc[3], av, w1.z, w1.w);
            a += 256; wl += 512;
        }
    }
}

// ---- one LSTM cell phase: K split x4 across kseg; symmetric smem reduce
//      (conflict-free [warp][elem][lane] layout); epilogue parallel across all
//      16 warps: warp (m,kseg) handles output set (m, nt=kseg). ----
__device__ __forceinline__ void cell_phase(
    const __half* __restrict__ Wb,
    const __half* __restrict__ A0, int n0,
    const __half* __restrict__ A1, int n1,
    const float*  __restrict__ bias,
    float& cr, __half* __restrict__ hout,
    float* __restrict__ red,
    int ct, int kseg, int m, int lane)
{
    float acc[4][4];
#pragma unroll
    for (int i = 0; i < 4; ++i)
#pragma unroll
        for (int k = 0; k < 4; ++k) acc[i][k] = 0.0f;

    const int nc  = n0 + n1;
    const int len = nc >> 2;                    // nc in {4,68,128}
    gemm_range(Wb, A0, n0, A1, kseg * len, kseg * len + len, acc, lane);

    __syncthreads();   // guard smem region reuse (prev phase reads done)
    // STS: red[warp16][elem16][lane32], lane-major = conflict-free
    {
        float* dst = red + (size_t)(kseg * 4 + m) * 512 + lane;
#pragma unroll
        for (int i = 0; i < 4; ++i)
#pragma unroll
            for (int k = 0; k < 4; ++k) dst[(i * 4 + k) * 32] = acc[i][k];
    }
    __syncthreads();

    // epilogue: this warp owns nt = kseg for batch tile m
    const int nt = kseg;
    float d[4];
#pragma unroll
    for (int k = 0; k < 4; ++k) {
        float s = 0.0f;
#pragma unroll
        for (int ks = 0; ks < 4; ++ks)
            s += red[(size_t)(ks * 4 + m) * 512 + (nt * 4 + k) * 32 + lane];
        d[k] = s;
    }

    const bool hi = (lane & 1);
    int j  = ct * 8 + 2 * nt + ((lane & 3) >> 1);
    int g0 = (lane & 1) * 2;
    float bv0 = __ldg(bias + g0 * 1024 + j);
    float bv1 = __ldg(bias + (g0 + 1) * 1024 + j);
    float d0 = d[0] + bv0, d1 = d[1] + bv1, d2 = d[2] + bv0, d3 = d[3] + bv1;

    float sA = hi ? d0 : d2;
    float sB = hi ? d1 : d3;
    float rA = __shfl_xor_sync(0xffffffffu, sA, 1);
    float rB = __shfl_xor_sync(0xffffffffu, sB, 1);
    float gi = hi ? rA : d0;
    float gf = hi ? rB : d1;
    float gc = hi ? d2 : rA;
    float go = hi ? d3 : rB;

    float cn = sigm(gf) * cr + sigm(gi) * tanh_f(gc);
    cr = cn;
    float hv = sigm(go) * tanh_f(cn);

    int b = m * 16 + (lane >> 2) + (hi ? 8 : 0);
    int ldst = ((b & 7) << 2) + ((j & 7) >> 1);
    int qq = (hi ? 1 : 0) + ((j & 8) ? 2 : 0);
    hout[(size_t)((b >> 4) * 64 + (j >> 4)) * 256 + ldst * 8 + qq * 2 + (j & 1)] =
        __float2half(hv);
}

// ---- main persistent kernel: skewed L0/L1 pipeline, 1 sync per encoder phase ----
__global__ void __launch_bounds__(NTHR, 1)
rnn_main_kernel(const float* __restrict__ b0, const float* __restrict__ b1,
                const float* __restrict__ bf, float* __restrict__ out)
{
    const int ct   = blockIdx.x;
    const int tid  = threadIdx.x;
    const int w    = tid >> 5;
    const int lane = tid & 31;
    const int m    = w & 3;
    const int kseg = w >> 2;

    float c0r = 0.f, c1r = 0.f;

    const __half* Wb0 = g_W0f + (size_t)ct * 68 * 512;
    const __half* Wb1 = g_W1f + (size_t)ct * 128 * 512;

    __shared__ float red[8192];   // 32 KB: [warp][elem][lane] reduce / proj scratch

    // h0(t) in g_H0F buffer (t&1); h1(t) in g_H1F (t&1).
    for (int p = 0; p <= 256; ++p) {
        if (p < 256) {
            const __half* a0    = g_XF + (size_t)(p * 4 + m) * 1024;
            const __half* h0old = g_H0F + (size_t)((((p - 1) & 1)) * 4 + m) * 16384;
            __half* h0out = g_H0F + (size_t)(p & 1) * 65536;
            cell_phase(Wb0, a0, 4, h0old, p ? 64 : 0, b0, c0r, h0out,
                       red, ct, kseg, m, lane);
        }
        if (p >= 1) {
            const int s1 = p - 1;
            const __half* h0new = g_H0F + (size_t)((s1 & 1) * 4 + m) * 16384;
            const __half* h1old = g_H1F + (size_t)((((s1 - 1) & 1)) * 4 + m) * 16384;
            __half* h1out = g_H1F + (size_t)(s1 & 1) * 65536;
            cell_phase(Wb1, h0new, 64, h1old, s1 ? 64 : 0, b1, c1r, h1out,
                       red, ct, kseg, m, lane);
        }
        grid_sync();
    }

    // Decoder: L0 | sync | L1 | sync | proj | sync
    for (int s = 256; s < 288; ++s) {
        const __half* a0 = (s == 256) ? g_XF + (size_t)(255 * 4 + m) * 1024
                                      : g_INPF + (size_t)m * 1024;
        cell_phase(Wb0, a0, 4,
                   g_H0F + (size_t)(((s - 1) & 1) * 4 + m) * 16384, 64, b0, c0r,
                   g_H0F + (size_t)(s & 1) * 65536, red, ct, kseg, m, lane);
        grid_sync();
        cell_phase(Wb1, g_H0F + (size_t)((s & 1) * 4 + m) * 16384, 64,
                   g_H1F + (size_t)(((s - 1) & 1) * 4 + m) * 16384, 64, b1, c1r,
                   g_H1F + (size_t)(s & 1) * 65536, red, ct, kseg, m, lane);
        grid_sync();

        float pacc[8];
        if (ct < 16 && w < 8) {
            const int mm = ct & 3, vg = ct >> 2;
            const __half* A  = g_H1F + (size_t)((s & 1) * 4 + mm) * 16384
                               + (size_t)(w * 8) * 256 + lane * 8;
            const __half* Wp = g_Wff + (size_t)(vg * 64 + w * 8) * 256 + lane * 8;
#pragma unroll
            for (int k = 0; k < 8; ++k) pacc[k] = 0.0f;
#pragma unroll
            for (int cc = 0; cc < 8; ++cc) {
                uint4 av = __ldcg((const uint4*)(A  + (size_t)cc * 256));
                uint4 wv = __ldg ((const uint4*)(Wp + (size_t)cc * 256));
                mma16816(pacc + 0, av, wv.x, wv.y);
                mma16816(pacc + 4, av, wv.z, wv.w);
            }
            if (w > 0) {
                float* dst = red + (size_t)(w - 1) * 256 + lane;
#pragma unroll
                for (int k = 0; k < 8; ++k) dst[k * 32] = pacc[k];
            }
        }
        __syncthreads();
        if (ct < 16 && w == 0) {
            float fsum[8];
#pragma unroll
            for (int k = 0; k < 8; ++k) fsum[k] = pacc[k];
#pragma unroll
            for (int ww = 1; ww < 8; ++ww) {
                const float* src = red + (size_t)(ww - 1) * 256 + lane;
#pragma unroll
                for (int k = 0; k < 8; ++k) fsum[k] += src[k * 32];
            }
            const int mm = ct & 3, vg = ct >> 2;
            const int tdec = s - TIN;
#pragma unroll
            for (int nt = 0; nt < 2; ++nt)
#pragma unroll
                for (int rr = 0; rr < 2; ++rr)
#pragma unroll
                    for (int e2 = 0; e2 < 2; ++e2) {
                        int b = mm * 16 + (lane >> 2) + rr * 8;
                        int v = vg * 16 + nt * 8 + ((lane & 3) << 1) + e2;
                        float val = fsum[nt * 4 + rr * 2 + e2] + __ldg(bf + v);
                        out[(size_t)(b * TOUT + tdec) * V_ + v] = val;
                        g_INPF[(size_t)((b >> 4) * 4 + (v >> 4)) * 256
                               + (((b & 7) << 2) + ((v & 7) >> 1)) * 8
                               + (rr + ((v & 8) ? 2 : 0)) * 2 + (v & 1)] =
                            __float2half(val);
                    }
        }
        grid_sync();
    }
}

extern "C" void kernel_launch(void* const* d_in, const int* in_sizes, int n_in,
                              void* d_out, int out_size) {
    const float* x  = (const float*)d_in[0];
    const float* W0 = (const float*)d_in[1];
    const float* b0 = (const float*)d_in[2];
    const float* W1 = (const float*)d_in[3];
    const float* b1 = (const float*)d_in[4];
    const float* Wf = (const float*)d_in[5];
    const float* bf = (const float*)d_in[6];
    float* out = (float*)d_out;

    prep_all<<<8192, 256>>>(x, W0, W1, Wf);
    rnn_main_kernel<<<NCTA, NTHR>>>(b0, b1, bf, out);
}